// round 14
// baseline (speedup 1.0000x reference)
#include <cuda_runtime.h>
#include <cuda_bf16.h>
#include <cstdint>

// Sparsemax over rows of [B=2048, V=32000] fp32.
// Persistent CTAs (1/SM, 1024 thr). cp.async.bulk (TMA) ring (7 x 32KB,
// lookahead staggered 7/6/5 by bid%3). Per row:
//   capture smem->regs (fused warp max, keep per-thread max tmt) ->
//   block max via 32-bit atomicMax(monotone key) -> sync A ->
//   EARLY ZERO-STORE: threads with tmt < th = rmax-1.0009 have provably
//   all-zero output (th < rmax-1 <= tau*) and store zeros immediately,
//   starting write traffic ~2K cycles earlier; candidate threads (~3%)
//   compact into smem -> sync B -> Michelot (register fast path, only in
//   warps containing a candidate thread) -> candidate threads store
//   max(x-tau,0). Refill keeps constant lookahead: rlim = depth+(lr+1)*4.

#define THREADS     1024
#define VROW        32000
#define NCHUNK      4
#define CHUNK_BYTES 32000
#define CHUNK_F4    2000
#define NSLOT       7
#define CAP         512
#define NEG_INF     (-3.4e38f)
#define SLACK       1.0009f

// dynamic smem layout (bytes)
#define OFF_BUF    0
#define OFF_CAND   (NSLOT * CHUNK_BYTES)          // 224000
#define OFF_NUM    (OFF_CAND + 2 * CAP * 4)       // 228096
#define OFF_MAXB   (OFF_NUM + 8)                  // 228104
#define OFF_MBAR   (OFF_MAXB + 8)                 // 228112 (8-aligned)
#define SMEM_TOTAL (OFF_MBAR + NSLOT * 8)         // 228168

__device__ __forceinline__ uint32_t smem_u32(const void* p) {
    return (uint32_t)__cvta_generic_to_shared(p);
}
__device__ __forceinline__ void mbar_init(uint32_t a, uint32_t cnt) {
    asm volatile("mbarrier.init.shared.b64 [%0], %1;" :: "r"(a), "r"(cnt) : "memory");
}
__device__ __forceinline__ void mbar_expect_tx(uint32_t a, uint32_t tx) {
    asm volatile("mbarrier.arrive.expect_tx.shared.b64 _, [%0], %1;"
                 :: "r"(a), "r"(tx) : "memory");
}
__device__ __forceinline__ void mbar_wait(uint32_t a, uint32_t parity) {
    asm volatile(
        "{\n\t"
        ".reg .pred P1;\n\t"
        "WAIT_LOOP_%=:\n\t"
        "mbarrier.try_wait.parity.acquire.cta.shared::cta.b64 P1, [%0], %1, 0x989680;\n\t"
        "@P1 bra.uni WAIT_DONE_%=;\n\t"
        "bra.uni WAIT_LOOP_%=;\n\t"
        "WAIT_DONE_%=:\n\t"
        "}"
        :: "r"(a), "r"(parity) : "memory");
}
__device__ __forceinline__ void bulk_g2s(uint32_t dst, const void* src,
                                         uint32_t bytes, uint32_t mbar) {
    asm volatile(
        "cp.async.bulk.shared::cta.global.mbarrier::complete_tx::bytes [%0], [%1], %2, [%3];"
        :: "r"(dst), "l"(src), "r"(bytes), "r"(mbar) : "memory");
}
__device__ __forceinline__ void fence_proxy_async() {
    asm volatile("fence.proxy.async;" ::: "memory");
}

// monotone float<->uint key: order-preserving for all finite floats
__device__ __forceinline__ unsigned fkey(float x) {
    unsigned u = __float_as_uint(x);
    return (u & 0x80000000u) ? ~u : (u | 0x80000000u);
}
__device__ __forceinline__ float funkey(unsigned k) {
    unsigned u = (k & 0x80000000u) ? (k ^ 0x80000000u) : ~k;
    return __uint_as_float(u);
}

__global__ __launch_bounds__(THREADS, 1)
void sparsemax_kernel(const float* __restrict__ in, float* __restrict__ out, int B)
{
    extern __shared__ char smem[];
    float*    cand   = (float*)(smem + OFF_CAND);       // [2][CAP]
    int*      s_num  = (int*)(smem + OFF_NUM);          // [2]
    unsigned* s_maxb = (unsigned*)(smem + OFF_MAXB);    // [2]
    const uint32_t mb = smem_u32(smem + OFF_MBAR);

    const int tid  = threadIdx.x;
    const int lane = tid & 31;
    const int bid  = blockIdx.x;
    const int G    = gridDim.x;
    const unsigned FULL = 0xffffffffu;

    if (bid >= B) return;

    const int nrows = (B - bid + G - 1) / G;
    const int Q = NCHUNK * nrows;

    if (tid == 0) {
        s_num[0] = 0;  s_num[1] = 0;
        s_maxb[0] = 0; s_maxb[1] = 0;
        for (int s = 0; s < NSLOT; ++s) mbar_init(mb + s * 8, 1);
        fence_proxy_async();
    }
    __syncthreads();

    // ---- prime the ring (lookahead staggered by bid to de-phase CTAs) ----
    int qi = 0;
    const int depth = NSLOT - (bid % 3);     // 7 / 6 / 5, all > NCHUNK
    if (tid == 0) {
        int lim = Q < depth ? Q : depth;
        for (; qi < lim; ++qi) {
            int lr2 = qi >> 2, ck = qi & 3;
            const char* src = (const char*)(in + (size_t)(bid + lr2 * G) * VROW)
                              + (size_t)ck * CHUNK_BYTES;
            uint32_t m = mb + (qi % NSLOT) * 8;
            mbar_expect_tx(m, CHUNK_BYTES);
            bulk_g2s(smem_u32(smem + OFF_BUF + (qi % NSLOT) * CHUNK_BYTES),
                     src, CHUNK_BYTES, m);
        }
    }

    for (int lr = 0; lr < nrows; ++lr) {
        const int row = bid + lr * G;
        const int p   = lr & 1;                 // parity buffer for this row
        float*    cbuf = cand + p * CAP;
        int rlim = depth + (lr + 1) * NCHUNK;   // constant-lookahead invariant
        if (rlim > Q) rlim = Q;

        // ---- capture row smem -> regs, fused max scan ----
        float4 v[8];
        float tm = NEG_INF;
#pragma unroll
        for (int k = 0; k < NCHUNK; ++k) {
            const int q = lr * NCHUNK + k;
            const int slot = q % NSLOT;
            mbar_wait(mb + slot * 8, (q / NSLOT) & 1);
            const float4* cb = (const float4*)(smem + OFF_BUF + slot * CHUNK_BYTES);
            v[2 * k] = cb[tid];
            tm = fmaxf(tm, fmaxf(fmaxf(v[2*k].x, v[2*k].y), fmaxf(v[2*k].z, v[2*k].w)));
            if (tid < CHUNK_F4 - THREADS) {     // tid < 976
                v[2 * k + 1] = cb[tid + THREADS];
                tm = fmaxf(tm, fmaxf(fmaxf(v[2*k+1].x, v[2*k+1].y),
                                     fmaxf(v[2*k+1].z, v[2*k+1].w)));
            } else {
                v[2 * k + 1] = make_float4(NEG_INF, NEG_INF, NEG_INF, NEG_INF);
            }
        }
        const float tmt = tm;                    // PER-THREAD max (pre-shuffle)

        // ---- block max: warp reduce + one 32-bit atomicMax per warp ----
#pragma unroll
        for (int o = 16; o; o >>= 1)
            tm = fmaxf(tm, __shfl_xor_sync(FULL, tm, o));
        if (lane == 0) atomicMax(&s_maxb[p], fkey(tm));
        __syncthreads();                         // sync A: max done, captures done

        const float rmax = funkey(s_maxb[p]);
        const float th = rmax - SLACK;           // th < rmax-1 <= tau*

        // tid0: reset other-parity state for NEXT row; refill this row's quota
        if (tid == 0) {
            s_num[p ^ 1] = 0;
            s_maxb[p ^ 1] = 0;
            for (; qi < rlim; ++qi) {
                int ilr = qi >> 2, ck = qi & 3;
                const char* src = (const char*)(in + (size_t)(bid + ilr * G) * VROW)
                                  + (size_t)ck * CHUNK_BYTES;
                uint32_t mm = mb + (qi % NSLOT) * 8;
                mbar_expect_tx(mm, CHUNK_BYTES);
                bulk_g2s(smem_u32(smem + OFF_BUF + (qi % NSLOT) * CHUNK_BYTES),
                         src, CHUNK_BYTES, mm);
            }
        }

        float4* orow = (float4*)(out + (size_t)row * VROW);
        const bool has_cand = (tmt >= th);

        if (!has_cand) {
            // ---- EARLY ZERO-STORE (~97% of threads): x < th < tau => out = 0.
            // Starts write traffic immediately; no dependence on tau.
            const float4 z = make_float4(0.0f, 0.0f, 0.0f, 0.0f);
#pragma unroll
            for (int k = 0; k < NCHUNK; ++k) {
                int idx = k * CHUNK_F4 + tid;
                __stcs(&orow[idx], z);
                if (tid < CHUNK_F4 - THREADS) __stcs(&orow[idx + THREADS], z);
            }
        } else {
            // ---- compact candidates (rare path) ----
            int c = 0;
#pragma unroll
            for (int i = 0; i < 8; ++i)
                c += (v[i].x >= th) + (v[i].y >= th) + (v[i].z >= th) + (v[i].w >= th);
            int base = atomicAdd(&s_num[p], c);
#pragma unroll
            for (int i = 0; i < 8; ++i) {
                float a4[4] = {v[i].x, v[i].y, v[i].z, v[i].w};
#pragma unroll
                for (int e = 0; e < 4; ++e)
                    if (a4[e] >= th) { if (base < CAP) cbuf[base] = a4[e]; ++base; }
            }
        }
        __syncthreads();                         // sync B: candidates complete

        // ---- Michelot only in warps that contain a candidate thread ----
        if (__any_sync(FULL, has_cand)) {
            const int n = s_num[p];
            float t = -1.0f;    // tau* >= -1 (shifted); support is y > tau*
            if (n <= 32) {
                // register fast path: lane holds one candidate
                float y = (lane < n) ? (cbuf[lane] - rmax) : -2.0f;
                int prev = -1;
                for (int itc = 0; itc < n + 2; ++itc) {
                    bool act = (y > t);
                    unsigned m = __ballot_sync(FULL, act);
                    int cnt = __popc(m);
                    float sum = act ? y : 0.0f;
#pragma unroll
                    for (int o = 16; o; o >>= 1)
                        sum += __shfl_xor_sync(FULL, sum, o);
                    if (cnt == prev) break;      // fixed point -> exact tau
                    prev = cnt;
                    t = (sum - 1.0f) / (float)cnt;
                }
            } else if (n <= CAP) {
                int prev = -1;
                for (int itc = 0; itc < n + 2; ++itc) {
                    float sum = 0.0f; int cnt = 0;
                    for (int i = lane; i < n; i += 32) {
                        float y = cbuf[i] - rmax;
                        if (y > t) { sum += y; cnt++; }
                    }
#pragma unroll
                    for (int o = 16; o; o >>= 1) {
                        sum += __shfl_xor_sync(FULL, sum, o);
                        cnt += __shfl_xor_sync(FULL, cnt, o);
                    }
                    if (cnt == prev) break;
                    prev = cnt;
                    t = (sum - 1.0f) / (float)cnt;
                }
            } else {
                // overflow fallback (degenerate inputs only): exact Michelot
                // over the full row from global memory.
                const float* rp = in + (size_t)row * VROW;
                t = -2.0f;
                int prev = -1;
                for (int itc = 0; itc < VROW; ++itc) {
                    float sum = 0.0f; int cnt = 0;
                    for (int i = lane; i < VROW; i += 32) {
                        float y = __ldg(&rp[i]) - rmax;
                        if (y > t) { sum += y; cnt++; }
                    }
#pragma unroll
                    for (int o = 16; o; o >>= 1) {
                        sum += __shfl_xor_sync(FULL, sum, o);
                        cnt += __shfl_xor_sync(FULL, cnt, o);
                    }
                    if (cnt == prev) break;
                    prev = cnt;
                    t = (sum - 1.0f) / (float)cnt;
                }
            }
            const float tau = rmax + t;

            // ---- candidate threads store their slice with the real formula ----
            if (has_cand) {
#pragma unroll
                for (int k = 0; k < NCHUNK; ++k) {
                    int idx = k * CHUNK_F4 + tid;
                    float4 r;
                    r.x = fmaxf(v[2*k].x - tau, 0.0f);
                    r.y = fmaxf(v[2*k].y - tau, 0.0f);
                    r.z = fmaxf(v[2*k].z - tau, 0.0f);
                    r.w = fmaxf(v[2*k].w - tau, 0.0f);
                    __stcs(&orow[idx], r);
                    if (tid < CHUNK_F4 - THREADS) {
                        float4 r2;
                        r2.x = fmaxf(v[2*k+1].x - tau, 0.0f);
                        r2.y = fmaxf(v[2*k+1].y - tau, 0.0f);
                        r2.z = fmaxf(v[2*k+1].z - tau, 0.0f);
                        r2.w = fmaxf(v[2*k+1].w - tau, 0.0f);
                        __stcs(&orow[idx + THREADS], r2);
                    }
                }
            }
        }
    }
}

extern "C" void kernel_launch(void* const* d_in, const int* in_sizes, int n_in,
                              void* d_out, int out_size)
{
    const float* in = (const float*)d_in[0];
    float* out = (float*)d_out;
    const int B = out_size / VROW;

    int sms = 148;
    cudaDeviceGetAttribute(&sms, cudaDevAttrMultiProcessorCount, 0);
    int G = sms;
    if (G > B) G = B;

    cudaFuncSetAttribute(sparsemax_kernel,
                         cudaFuncAttributeMaxDynamicSharedMemorySize, SMEM_TOTAL);
    sparsemax_kernel<<<G, THREADS, SMEM_TOTAL>>>(in, out, B);
}